// round 7
// baseline (speedup 1.0000x reference)
#include <cuda_runtime.h>
#include <cooperative_groups.h>
#include <math.h>

namespace cg = cooperative_groups;

#define T_STEPS  2000
#define BATCH    512
#define HID      128
#define CLUSTER_N 4
#define NCLUSTERS 32
#define THREADS  256
#define BC       16      // batch rows per cluster

// Scratch: layer0 hidden sequence + final layer1 hidden state
__device__ float g_h1[(size_t)T_STEPS * BATCH * HID];
__device__ float g_h2last[BATCH * HID];

__device__ __forceinline__ float sigmoidf_(float v) { return 1.0f / (1.0f + expf(-v)); }

// One persistent scan kernel per LSTM layer.
// Cluster of 4 CTAs handles BC=16 batch rows. CTA rank r owns gate columns
// [128r, 128r+128). Weights stay in SMEM for the whole scan.
// opd[b][0:128)   = recurrent hidden state h (replicated per CTA)
// opd[b][128:...) = per-step input (x_t for layer0, h1_t for layer1)
template<int K_IN, int K_OP, bool IS_L0>
__global__ __launch_bounds__(THREADS, 1) __cluster_dims__(CLUSTER_N, 1, 1)
void lstm_scan(const float* __restrict__ W_ih, const float* __restrict__ W_hh,
               const float* __restrict__ b_ih, const float* __restrict__ b_hh,
               const float* __restrict__ x)
{
    extern __shared__ float sm[];
    float* w_s    = sm;                         // [K_OP][128], w_s[k][c]
    float* opd    = w_s + K_OP * 128;           // [BC][K_OP]
    float* gate_s = opd + BC * K_OP;            // [BC][128]
    float* bias_s = gate_s + BC * 128;          // [128]

    cg::cluster_group cluster = cg::this_cluster();
    const int rank = (int)cluster.block_rank();
    const int tid  = threadIdx.x;
    const int cid  = blockIdx.x / CLUSTER_N;
    const int B0   = cid * BC;

    // ---- one-time weight / bias load into SMEM (transposed: w_s[k][c]) ----
    for (int idx = tid; idx < K_OP * 128; idx += THREADS) {
        int k = idx >> 7, c = idx & 127;
        int gc = rank * 128 + c;
        float v;
        if (k < HID) {
            v = W_hh[gc * HID + k];
        } else {
            int ki = k - HID;
            v = (ki < K_IN) ? W_ih[gc * K_IN + ki] : 0.0f;
        }
        w_s[idx] = v;
    }
    if (tid < 128) bias_s[tid] = b_ih[rank * 128 + tid] + b_hh[rank * 128 + tid];
    for (int idx = tid; idx < BC * K_OP; idx += THREADS) opd[idx] = 0.0f;
    __syncthreads();

    // DSMEM-mapped base pointers for all 4 cluster ranks
    float* gateR[4];
    float* opdR[4];
    #pragma unroll
    for (int d = 0; d < 4; ++d) {
        gateR[d] = (float*)cluster.map_shared_rank((void*)gate_s, d);
        opdR[d]  = (float*)cluster.map_shared_rank((void*)opd, d);
    }

    // GEMM thread mapping: 8 warps; warp = (row-group r0, k-half kh)
    const int lane = tid & 31, warp = tid >> 5;
    const int c0 = lane * 4;           // 4 consecutive gate cols
    const int r0 = warp & 3;           // rows r0 + 4i, i=0..3
    const int kh = warp >> 2;          // k-half
    const int kbeg = kh * (K_OP / 2);
    const int kend = kbeg + (K_OP / 2);

    float binit[4];
    #pragma unroll
    for (int j = 0; j < 4; ++j) binit[j] = (kh == 0) ? bias_s[c0 + j] : 0.0f;

    // Pointwise mapping: thread -> column jj, handles rows q = qb and qb+2
    const int jj = tid & 127;
    const int qb = tid >> 7;
    float creg[2] = {0.0f, 0.0f};

    constexpr int NPF = IS_L0 ? 1 : 8;
    float pf[NPF];

    auto prefetch = [&](int t) {
        if constexpr (IS_L0) {
            if (tid < BC * 13) {
                int b = tid / 13, i = tid - b * 13;
                pf[0] = x[((size_t)(B0 + b) * T_STEPS + t) * 13 + i];
            }
        } else {
            #pragma unroll
            for (int i = 0; i < 8; ++i) {
                int b = qb + 2 * i;
                pf[i] = g_h1[((size_t)t * BATCH + B0 + b) * HID + jj];
            }
        }
    };

    prefetch(0);

    for (int t = 0; t < T_STEPS; ++t) {
        // ---- stage this step's input term into opd[b][128:...) ----
        if constexpr (IS_L0) {
            if (tid < BC * 13) {
                int b = tid / 13, i = tid - b * 13;
                opd[b * K_OP + HID + i] = pf[0];
            }
        } else {
            #pragma unroll
            for (int i = 0; i < 8; ++i) {
                int b = qb + 2 * i;
                opd[b * K_OP + HID + jj] = pf[i];
            }
        }
        __syncthreads();

        // prefetch next step's input (hidden behind the GEMM)
        if (t + 1 < T_STEPS) prefetch(t + 1);

        // ---- gate GEMM: gate_s[b][c] = bias + sum_k w_s[k][c] * opd[b][k] ----
        float acc[4][4];
        #pragma unroll
        for (int i = 0; i < 4; ++i)
            #pragma unroll
            for (int j = 0; j < 4; ++j) acc[i][j] = binit[j];

        #pragma unroll 4
        for (int k = kbeg; k < kend; ++k) {
            const float4 wv = *reinterpret_cast<const float4*>(&w_s[(k << 7) + c0]);
            #pragma unroll
            for (int i = 0; i < 4; ++i) {
                float a = opd[(r0 + (i << 2)) * K_OP + k];   // warp-uniform broadcast
                acc[i][0] = fmaf(a, wv.x, acc[i][0]);
                acc[i][1] = fmaf(a, wv.y, acc[i][1]);
                acc[i][2] = fmaf(a, wv.z, acc[i][2]);
                acc[i][3] = fmaf(a, wv.w, acc[i][3]);
            }
        }

        if (kh == 0) {
            #pragma unroll
            for (int i = 0; i < 4; ++i)
                *reinterpret_cast<float4*>(&gate_s[(r0 + (i << 2)) * 128 + c0]) =
                    make_float4(acc[i][0], acc[i][1], acc[i][2], acc[i][3]);
        }
        __syncthreads();
        if (kh == 1) {
            #pragma unroll
            for (int i = 0; i < 4; ++i) {
                float4* gp = reinterpret_cast<float4*>(&gate_s[(r0 + (i << 2)) * 128 + c0]);
                float4 g = *gp;
                g.x += acc[i][0]; g.y += acc[i][1]; g.z += acc[i][2]; g.w += acc[i][3];
                *gp = g;
            }
        }
        cluster.sync();   // gates visible cluster-wide

        // ---- pointwise LSTM update for this CTA's batch quarter ----
        #pragma unroll
        for (int s = 0; s < 2; ++s) {
            int q = qb + 2 * s;
            int b = 4 * rank + q;            // cluster-local batch row
            int off = b * 128 + jj;
            float gi = gateR[0][off];        // i gate (cols   0..127 -> rank 0)
            float gf = gateR[1][off];        // f gate (cols 128..255 -> rank 1)
            float gg = gateR[2][off];        // g gate (cols 256..383 -> rank 2)
            float go = gateR[3][off];        // o gate (cols 384..511 -> rank 3)
            float c = sigmoidf_(gf) * creg[s] + sigmoidf_(gi) * tanhf(gg);
            creg[s] = c;
            float h = sigmoidf_(go) * tanhf(c);
            #pragma unroll
            for (int d = 0; d < 4; ++d) opdR[d][b * K_OP + jj] = h;  // replicate h
            if constexpr (IS_L0) {
                g_h1[((size_t)t * BATCH + (B0 + b)) * HID + jj] = h;
            } else {
                if (t == T_STEPS - 1) g_h2last[(B0 + b) * HID + jj] = h;
            }
        }
        cluster.sync();   // h replicated before next GEMM; keeps peers' SMEM alive
    }
}

__global__ void fc_kernel(const float* __restrict__ Wfc, const float* __restrict__ bfc,
                          float* __restrict__ out)
{
    __shared__ float w[4][128];
    int tid = threadIdx.x;
    for (int idx = tid; idx < 512; idx += 128) w[idx >> 7][idx & 127] = Wfc[idx];
    __syncthreads();
    int b = blockIdx.x * 128 + tid;
    float s[4];
    #pragma unroll
    for (int cc = 0; cc < 4; ++cc) s[cc] = bfc[cc];
    #pragma unroll 4
    for (int k = 0; k < 128; ++k) {
        float h = g_h2last[b * 128 + k];
        #pragma unroll
        for (int cc = 0; cc < 4; ++cc) s[cc] = fmaf(h, w[cc][k], s[cc]);
    }
    #pragma unroll
    for (int cc = 0; cc < 4; ++cc) out[b * 4 + cc] = s[cc];
}

extern "C" void kernel_launch(void* const* d_in, const int* in_sizes, int n_in,
                              void* d_out, int out_size)
{
    (void)in_sizes; (void)n_in; (void)out_size;
    const float* x    = (const float*)d_in[0];
    const float* Wih0 = (const float*)d_in[1];
    const float* Whh0 = (const float*)d_in[2];
    const float* bih0 = (const float*)d_in[3];
    const float* bhh0 = (const float*)d_in[4];
    const float* Wih1 = (const float*)d_in[5];
    const float* Whh1 = (const float*)d_in[6];
    const float* bih1 = (const float*)d_in[7];
    const float* bhh1 = (const float*)d_in[8];
    const float* Wfc  = (const float*)d_in[9];
    const float* bfc  = (const float*)d_in[10];
    float* out = (float*)d_out;

    // layer0: K_OP = 128 (h) + 16 (x padded from 13) = 144
    // layer1: K_OP = 128 (h2) + 128 (h1) = 256
    const int smem0 = (144 * 128 + BC * 144 + BC * 128 + 128) * (int)sizeof(float);
    const int smem1 = (256 * 128 + BC * 256 + BC * 128 + 128) * (int)sizeof(float);

    cudaFuncSetAttribute((const void*)lstm_scan<13, 144, true>,
                         cudaFuncAttributeMaxDynamicSharedMemorySize, smem0);
    cudaFuncSetAttribute((const void*)lstm_scan<128, 256, false>,
                         cudaFuncAttributeMaxDynamicSharedMemorySize, smem1);

    lstm_scan<13, 144, true><<<NCLUSTERS * CLUSTER_N, THREADS, smem0>>>(
        Wih0, Whh0, bih0, bhh0, x);
    lstm_scan<128, 256, false><<<NCLUSTERS * CLUSTER_N, THREADS, smem1>>>(
        Wih1, Whh1, bih1, bhh1, nullptr);
    fc_kernel<<<4, 128>>>(Wfc, bfc, out);
}

// round 9
// speedup vs baseline: 1.2522x; 1.2522x over previous
#include <cuda_runtime.h>
#include <cooperative_groups.h>
#include <math.h>

namespace cg = cooperative_groups;

#define T_STEPS  2000
#define BATCH    512
#define HID      128
#define CLUSTER_N 4
#define NCLUSTERS 32
#define THREADS  512
#define BC       16      // batch rows per cluster

typedef unsigned long long ull;

// Scratch: layer0 hidden sequence + final layer1 hidden state
__device__ float g_h1[(size_t)T_STEPS * BATCH * HID];
__device__ float g_h2last[BATCH * HID];

__device__ __forceinline__ float tanh_f(float x) {
    float y; asm("tanh.approx.f32 %0, %1;" : "=f"(y) : "f"(x)); return y;
}
__device__ __forceinline__ float sig_f(float x) {
    float e; asm("ex2.approx.f32 %0, %1;" : "=f"(e) : "f"(-1.4426950408889634f * x));
    float d = 1.0f + e, r;
    asm("rcp.approx.f32 %0, %1;" : "=f"(r) : "f"(d));
    return r;
}
#define FMA2(d, a, b) asm("fma.rn.f32x2 %0, %1, %2, %0;" : "+l"(d) : "l"(a), "l"(b))
#define PACK_DUP(d, f) asm("mov.b64 %0, {%1, %1};" : "=l"(d) : "f"(f))

// Persistent scan, one kernel per LSTM layer.
// Cluster of 4 CTAs handles BC=16 batch rows; CTA rank r owns gate columns
// [128r, 128r+128). Weights live in SMEM for the whole scan (transposed
// w_s[k][c]). opd[b][0:128) = recurrent h (replicated in every CTA),
// opd[b][128:K_OP) = per-step input (x_t padded for layer0, h1_t for layer1).
// GEMM: 16 warps = 4 row-groups x 4 K-quarters, f32x2 packed column pairs.
template<int K_IN, int K_OP, bool IS_L0>
__global__ __launch_bounds__(THREADS, 1) __cluster_dims__(CLUSTER_N, 1, 1)
void lstm_scan(const float* __restrict__ W_ih, const float* __restrict__ W_hh,
               const float* __restrict__ b_ih, const float* __restrict__ b_hh,
               const float* __restrict__ x)
{
    extern __shared__ float sm[];
    float* w_s    = sm;                          // [K_OP][128]
    float* opd    = w_s + K_OP * 128;            // [BC][K_OP]
    float* gate_s = opd + BC * K_OP;             // [BC][128]
    float* part   = gate_s + BC * 128;           // [3][BC][128]
    float* bias_s = part + 3 * BC * 128;         // [128]

    cg::cluster_group cluster = cg::this_cluster();
    const int rank = (int)cluster.block_rank();
    const int tid  = threadIdx.x;
    const int cid  = blockIdx.x / CLUSTER_N;
    const int B0   = cid * BC;

    // ---- one-time weight / bias load (transposed) ----
    for (int idx = tid; idx < K_OP * 128; idx += THREADS) {
        int k = idx >> 7, c = idx & 127;
        int gc = rank * 128 + c;
        float v;
        if (k < HID) v = W_hh[gc * HID + k];
        else { int ki = k - HID; v = (ki < K_IN) ? W_ih[gc * K_IN + ki] : 0.0f; }
        w_s[idx] = v;
    }
    if (tid < 128) bias_s[tid] = b_ih[rank * 128 + tid] + b_hh[rank * 128 + tid];
    for (int idx = tid; idx < BC * K_OP; idx += THREADS) opd[idx] = 0.0f;
    __syncthreads();

    // DSMEM-mapped peer pointers
    float* gateR[4];
    float* opdR[4];
    #pragma unroll
    for (int d = 0; d < 4; ++d) {
        gateR[d] = (float*)cluster.map_shared_rank((void*)gate_s, d);
        opdR[d]  = (float*)cluster.map_shared_rank((void*)opd, d);
    }

    // GEMM mapping: 16 warps = 4 row-groups x 4 K-quarters
    const int lane = tid & 31, warp = tid >> 5;
    const int c0   = lane * 4;            // 4 consecutive gate columns
    const int r0   = warp & 3;            // rows r0 + 4i, i=0..3
    const int kq   = warp >> 2;           // K quarter 0..3
    const int kbeg = kq * (K_OP / 4);
    const int kend = kbeg + (K_OP / 4);

    ull binit0 = 0, binit1 = 0;
    if (kq == 0) {
        ulonglong2 bv = *reinterpret_cast<const ulonglong2*>(&bias_s[c0]);
        binit0 = bv.x; binit1 = bv.y;
    }

    // Pointwise mapping: 1 element per thread. jj = column, q = local row 0..3
    const int jj = tid & 127;
    const int q  = tid >> 7;
    float creg = 0.0f;

    constexpr int NPF = IS_L0 ? 1 : 4;
    float pf[NPF];

    auto prefetch = [&](int t) {
        if constexpr (IS_L0) {
            if (tid < BC * 13) {
                int b = tid / 13, i = tid - b * 13;
                pf[0] = x[((size_t)(B0 + b) * T_STEPS + t) * 13 + i];
            }
        } else {
            #pragma unroll
            for (int i = 0; i < 4; ++i)
                pf[i] = g_h1[((size_t)t * BATCH + B0 + q + 4 * i) * HID + jj];
        }
    };
    auto stage = [&]() {
        if constexpr (IS_L0) {
            if (tid < BC * 13) {
                int b = tid / 13, i = tid - b * 13;
                opd[b * K_OP + HID + i] = pf[0];
            }
        } else {
            #pragma unroll
            for (int i = 0; i < 4; ++i)
                opd[(q + 4 * i) * K_OP + HID + jj] = pf[i];
        }
    };

    prefetch(0);
    stage();
    __syncthreads();

    for (int t = 0; t < T_STEPS; ++t) {
        // issue next step's input loads early; consumed at the staging point
        if (t + 1 < T_STEPS) prefetch(t + 1);

        // ---- gate GEMM: per-thread 4 rows x 4 cols (2 f32x2 pairs) ----
        ull acc[4][2];
        #pragma unroll
        for (int i = 0; i < 4; ++i) { acc[i][0] = binit0; acc[i][1] = binit1; }

        const float* orow0 = &opd[(r0 + 0)  * K_OP];
        const float* orow1 = &opd[(r0 + 4)  * K_OP];
        const float* orow2 = &opd[(r0 + 8)  * K_OP];
        const float* orow3 = &opd[(r0 + 12) * K_OP];

        #pragma unroll 4
        for (int k = kbeg; k < kend; ++k) {
            ulonglong2 wv = *reinterpret_cast<const ulonglong2*>(&w_s[(k << 7) + c0]);
            ull aa;
            PACK_DUP(aa, orow0[k]); FMA2(acc[0][0], aa, wv.x); FMA2(acc[0][1], aa, wv.y);
            PACK_DUP(aa, orow1[k]); FMA2(acc[1][0], aa, wv.x); FMA2(acc[1][1], aa, wv.y);
            PACK_DUP(aa, orow2[k]); FMA2(acc[2][0], aa, wv.x); FMA2(acc[2][1], aa, wv.y);
            PACK_DUP(aa, orow3[k]); FMA2(acc[3][0], aa, wv.x); FMA2(acc[3][1], aa, wv.y);
        }

        // store partials: kq==0 straight into gate_s (with bias), others to part
        float* dst = (kq == 0) ? gate_s : &part[(kq - 1) * BC * 128];
        #pragma unroll
        for (int i = 0; i < 4; ++i) {
            ulonglong2 v; v.x = acc[i][0]; v.y = acc[i][1];
            *reinterpret_cast<ulonglong2*>(&dst[(r0 + (i << 2)) * 128 + c0]) = v;
        }
        __syncthreads();

        // combine 4 partials (1 float4 per thread: 512 x 4 = 2048 gate values)
        {
            float4* g4 = reinterpret_cast<float4*>(gate_s);
            float4* p4 = reinterpret_cast<float4*>(part);
            float4 g = g4[tid];
            float4 a0 = p4[tid], a1 = p4[512 + tid], a2 = p4[1024 + tid];
            g.x += a0.x + a1.x + a2.x;
            g.y += a0.y + a1.y + a2.y;
            g.z += a0.z + a1.z + a2.z;
            g.w += a0.w + a1.w + a2.w;
            g4[tid] = g;
        }
        cluster.sync();   // gates visible cluster-wide

        // ---- pointwise update: this CTA owns cluster rows [4*rank, 4*rank+4) ----
        {
            int b   = 4 * rank + q;
            int off = b * 128 + jj;
            float gi = gateR[0][off];
            float gf = gateR[1][off];
            float gg = gateR[2][off];
            float go = gateR[3][off];
            float c = sig_f(gf) * creg + sig_f(gi) * tanh_f(gg);
            creg = c;
            float h = sig_f(go) * tanh_f(c);
            #pragma unroll
            for (int d = 0; d < 4; ++d) opdR[d][b * K_OP + jj] = h;
            if constexpr (IS_L0) {
                g_h1[((size_t)t * BATCH + (B0 + b)) * HID + jj] = h;
            } else {
                if (t == T_STEPS - 1) g_h2last[(B0 + b) * HID + jj] = h;
            }
        }

        // stage next step's input into own opd (covered by the cluster.sync)
        if (t + 1 < T_STEPS) stage();

        cluster.sync();   // h replicated + input staged before next GEMM
    }
}

__global__ void fc_kernel(const float* __restrict__ Wfc, const float* __restrict__ bfc,
                          float* __restrict__ out)
{
    __shared__ float w[4][128];
    int tid = threadIdx.x;
    for (int idx = tid; idx < 512; idx += 128) w[idx >> 7][idx & 127] = Wfc[idx];
    __syncthreads();
    int b = blockIdx.x * 128 + tid;
    float s[4];
    #pragma unroll
    for (int cc = 0; cc < 4; ++cc) s[cc] = bfc[cc];
    #pragma unroll 4
    for (int k = 0; k < 128; ++k) {
        float h = g_h2last[b * 128 + k];
        #pragma unroll
        for (int cc = 0; cc < 4; ++cc) s[cc] = fmaf(h, w[cc][k], s[cc]);
    }
    #pragma unroll
    for (int cc = 0; cc < 4; ++cc) out[b * 4 + cc] = s[cc];
}

extern "C" void kernel_launch(void* const* d_in, const int* in_sizes, int n_in,
                              void* d_out, int out_size)
{
    (void)in_sizes; (void)n_in; (void)out_size;
    const float* x    = (const float*)d_in[0];
    const float* Wih0 = (const float*)d_in[1];
    const float* Whh0 = (const float*)d_in[2];
    const float* bih0 = (const float*)d_in[3];
    const float* bhh0 = (const float*)d_in[4];
    const float* Wih1 = (const float*)d_in[5];
    const float* Whh1 = (const float*)d_in[6];
    const float* bih1 = (const float*)d_in[7];
    const float* bhh1 = (const float*)d_in[8];
    const float* Wfc  = (const float*)d_in[9];
    const float* bfc  = (const float*)d_in[10];
    float* out = (float*)d_out;

    // layer0: K_OP = 128 (h) + 16 (x padded from 13) = 144
    // layer1: K_OP = 128 (h2) + 128 (h1) = 256
    const int smem0 = (144 * 128 + BC * 144 + 4 * BC * 128 + 128) * (int)sizeof(float);
    const int smem1 = (256 * 128 + BC * 256 + 4 * BC * 128 + 128) * (int)sizeof(float);

    cudaFuncSetAttribute((const void*)lstm_scan<13, 144, true>,
                         cudaFuncAttributeMaxDynamicSharedMemorySize, smem0);
    cudaFuncSetAttribute((const void*)lstm_scan<128, 256, false>,
                         cudaFuncAttributeMaxDynamicSharedMemorySize, smem1);

    lstm_scan<13, 144, true><<<NCLUSTERS * CLUSTER_N, THREADS, smem0>>>(
        Wih0, Whh0, bih0, bhh0, x);
    lstm_scan<128, 256, false><<<NCLUSTERS * CLUSTER_N, THREADS, smem1>>>(
        Wih1, Whh1, bih1, bhh1, nullptr);
    fc_kernel<<<4, 128>>>(Wfc, bfc, out);
}

// round 10
// speedup vs baseline: 1.4553x; 1.1622x over previous
#include <cuda_runtime.h>
#include <cooperative_groups.h>
#include <math.h>

namespace cg = cooperative_groups;

#define T_STEPS  2000
#define BATCH    512
#define HID      128
#define CLUSTER_N 4
#define NCLUSTERS 32
#define THREADS  512
#define BC       16      // batch rows per cluster

typedef unsigned long long ull;

// Scratch: layer0 hidden sequence + final layer1 hidden state
__device__ float g_h1[(size_t)T_STEPS * BATCH * HID];
__device__ float g_h2last[BATCH * HID];

__device__ __forceinline__ float tanh_f(float x) {
    float y; asm("tanh.approx.f32 %0, %1;" : "=f"(y) : "f"(x)); return y;
}
__device__ __forceinline__ float sig_f(float x) {
    float e; asm("ex2.approx.f32 %0, %1;" : "=f"(e) : "f"(-1.4426950408889634f * x));
    float d = 1.0f + e, r;
    asm("rcp.approx.f32 %0, %1;" : "=f"(r) : "f"(d));
    return r;
}
#define FMA2(d, a, b) asm("fma.rn.f32x2 %0, %1, %2, %0;" : "+l"(d) : "l"(a), "l"(b))
#define PACK_DUP(d, f) asm("mov.b64 %0, {%1, %1};" : "=l"(d) : "f"(f))

__device__ __forceinline__ void mbar_init(unsigned addr, unsigned count) {
    asm volatile("mbarrier.init.shared.b64 [%0], %1;" :: "r"(addr), "r"(count) : "memory");
}
// arrive (release, cluster scope) on rank `rk`'s barrier at the same smem offset
__device__ __forceinline__ void mbar_arrive_rank(unsigned addr, unsigned rk) {
    asm volatile(
        "{\n\t.reg .b32 ra;\n\t"
        "mapa.shared::cluster.u32 ra, %0, %1;\n\t"
        "mbarrier.arrive.release.cluster.shared::cluster.b64 _, [ra];\n\t}"
        :: "r"(addr), "r"(rk) : "memory");
}
__device__ __forceinline__ void mbar_wait_par(unsigned addr, unsigned par) {
    asm volatile(
        "{\n\t.reg .pred P;\n\t"
        "LW%=:\n\t"
        "mbarrier.try_wait.parity.acquire.cluster.shared::cta.b64 P, [%0], %1, 0x989680;\n\t"
        "@P bra LD%=;\n\t"
        "bra LW%=;\n\t"
        "LD%=:\n\t}"
        :: "r"(addr), "r"(par) : "memory");
}

// Persistent scan, one kernel per LSTM layer.
// Cluster of 4 CTAs handles BC=16 batch rows. CTA rank r owns, for EVERY gate
// g in {i,f,g,o}, output columns [32r, 32r+32): local col c128 = g*32 + c maps
// to global W row g*128 + 32r + c. So the pointwise LSTM update is fully
// CTA-local; only h (16x32 per CTA) is replicated to peers via DSMEM.
// opd is DOUBLE-BUFFERED: GEMM(t) reads buffer t&1 while pointwise(t) writes
// h(t) into buffer (t+1)&1 -> no cross-CTA WAR hazard, so ONE cluster barrier
// per step (mbarrier arrive/wait, no cluster.sync L1-flush).
// GEMM: 16 warps = 8 K-chunks x 2 row-groups (8 rows each), 4 cols/lane,
// f32x2 packed FMA, float4 broadcast a-loads. 8 partial buffers combined
// inside the pointwise pass.
template<int K_IN, int K_OP, bool IS_L0>
__global__ __launch_bounds__(THREADS, 1) __cluster_dims__(CLUSTER_N, 1, 1)
void lstm_scan(const float* __restrict__ W_ih, const float* __restrict__ W_hh,
               const float* __restrict__ b_ih, const float* __restrict__ b_hh,
               const float* __restrict__ x)
{
    constexpr int KC = K_OP / 8;                 // k per chunk (20 / 32)
    extern __shared__ float sm[];
    float* w_s    = sm;                          // [K_OP][128]
    float* opd    = w_s + K_OP * 128;            // [2][BC][K_OP]
    float* part   = opd + 2 * BC * K_OP;         // [8][BC][128]
    float* bias_s = part + 8 * BC * 128;         // [128]
    ull*   mbarp  = (ull*)(bias_s + 128);        // 1 mbarrier

    cg::cluster_group cluster = cg::this_cluster();
    const int rank = (int)cluster.block_rank();
    const int tid  = threadIdx.x;
    const int cid  = blockIdx.x / CLUSTER_N;
    const int B0   = cid * BC;
    const unsigned mbar_a = (unsigned)__cvta_generic_to_shared(mbarp);

    // ---- one-time weight / bias load (gate-interleaved columns, transposed) ----
    for (int idx = tid; idx < K_OP * 128; idx += THREADS) {
        int k = idx >> 7, c128 = idx & 127;
        int g = c128 >> 5, c = c128 & 31;
        int gc = g * 128 + 32 * rank + c;        // global W row
        float v;
        if (k < HID) v = W_hh[gc * HID + k];
        else { int ki = k - HID; v = (ki < K_IN) ? W_ih[gc * K_IN + ki] : 0.0f; }
        w_s[idx] = v;
    }
    if (tid < 128) {
        int g = tid >> 5, c = tid & 31;
        int gc = g * 128 + 32 * rank + c;
        bias_s[tid] = b_ih[gc] + b_hh[gc];
    }
    for (int idx = tid; idx < 2 * BC * K_OP; idx += THREADS) opd[idx] = 0.0f;
    if (tid == 0) mbar_init(mbar_a, 4);
    __syncthreads();
    cluster.sync();   // mbarriers + zeroed opd visible cluster-wide

    // DSMEM peer pointers to opd
    float* opdR[4];
    #pragma unroll
    for (int d = 0; d < 4; ++d)
        opdR[d] = (float*)cluster.map_shared_rank((void*)opd, d);

    // GEMM mapping: warp = (kq, rg); kq = K chunk 0..7, rg = row half 0..1
    const int lane = tid & 31, warp = tid >> 5;
    const int c0   = lane * 4;                   // 4 consecutive local cols
    const int kq   = warp >> 1;
    const int rg   = warp & 1;
    const int kbeg = kq * KC;
    float* pdst = part + kq * (BC * 128);

    // Pointwise mapping: thread -> (batch row b, col jj within the 32-col slice)
    const int b  = tid >> 5;
    const int jj = tid & 31;
    float creg = 0.0f;

    constexpr int NPF = IS_L0 ? 1 : 4;
    float pf[NPF];
    int sb = 0, si = 0;
    if constexpr (IS_L0) { sb = tid / 13; si = tid - sb * 13; }

    auto prefetch = [&](int t) {
        if constexpr (IS_L0) {
            if (tid < BC * 13)
                pf[0] = x[((size_t)(B0 + sb) * T_STEPS + t) * 13 + si];
        } else {
            #pragma unroll
            for (int i = 0; i < 4; ++i)
                pf[i] = g_h1[((size_t)t * BATCH + B0 + b) * HID + jj + 32 * i];
        }
    };
    auto stage = [&](int buf) {
        float* dst = opd + buf * (BC * K_OP);
        if constexpr (IS_L0) {
            if (tid < BC * 13) dst[sb * K_OP + HID + si] = pf[0];
        } else {
            #pragma unroll
            for (int i = 0; i < 4; ++i)
                dst[b * K_OP + HID + jj + 32 * i] = pf[i];
        }
    };

    prefetch(0);
    stage(0);
    __syncthreads();

    for (int t = 0; t < T_STEPS; ++t) {
        const int p = t & 1;
        if (t + 1 < T_STEPS) prefetch(t + 1);

        // ---- gate GEMM partials: 8 rows x 4 cols per thread ----
        ull acc[8][2];
        #pragma unroll
        for (int i = 0; i < 8; ++i) { acc[i][0] = 0ULL; acc[i][1] = 0ULL; }

        const float* ob = opd + p * (BC * K_OP) + rg * 8 * K_OP;

        #pragma unroll 2
        for (int k4 = kbeg; k4 < kbeg + KC; k4 += 4) {
            float4 a4[8];
            #pragma unroll
            for (int i = 0; i < 8; ++i)
                a4[i] = *reinterpret_cast<const float4*>(&ob[i * K_OP + k4]);
            #pragma unroll
            for (int kk = 0; kk < 4; ++kk) {
                ulonglong2 wv =
                    *reinterpret_cast<const ulonglong2*>(&w_s[((k4 + kk) << 7) + c0]);
                #pragma unroll
                for (int i = 0; i < 8; ++i) {
                    float av = (kk == 0) ? a4[i].x : (kk == 1) ? a4[i].y
                             : (kk == 2) ? a4[i].z : a4[i].w;
                    ull aa; PACK_DUP(aa, av);
                    FMA2(acc[i][0], aa, wv.x);
                    FMA2(acc[i][1], aa, wv.y);
                }
            }
        }
        #pragma unroll
        for (int i = 0; i < 8; ++i) {
            ulonglong2 v; v.x = acc[i][0]; v.y = acc[i][1];
            *reinterpret_cast<ulonglong2*>(&pdst[(rg * 8 + i) * 128 + c0]) = v;
        }
        __syncthreads();

        // ---- pointwise: combine 8 partials + bias, LSTM update (all local) ----
        {
            float gs0 = bias_s[jj], gs1 = bias_s[32 + jj],
                  gs2 = bias_s[64 + jj], gs3 = bias_s[96 + jj];
            #pragma unroll
            for (int q = 0; q < 8; ++q) {
                const float* pp = part + q * (BC * 128) + b * 128 + jj;
                gs0 += pp[0]; gs1 += pp[32]; gs2 += pp[64]; gs3 += pp[96];
            }
            float c = sig_f(gs1) * creg + sig_f(gs0) * tanh_f(gs2);
            creg = c;
            float h = sig_f(gs3) * tanh_f(c);
            int hoff = (p ^ 1) * (BC * K_OP) + b * K_OP + 32 * rank + jj;
            #pragma unroll
            for (int d = 0; d < 4; ++d) opdR[d][hoff] = h;
            if constexpr (IS_L0) {
                g_h1[((size_t)t * BATCH + B0 + b) * HID + 32 * rank + jj] = h;
            } else {
                if (t == T_STEPS - 1)
                    g_h2last[(B0 + b) * HID + 32 * rank + jj] = h;
            }
        }
        if (t + 1 < T_STEPS) stage(p ^ 1);

        __syncthreads();                       // all local + DSMEM stores ordered
        if (tid < 4) mbar_arrive_rank(mbar_a, (unsigned)tid);
        mbar_wait_par(mbar_a, (unsigned)(t & 1));
    }
}

__global__ void fc_kernel(const float* __restrict__ Wfc, const float* __restrict__ bfc,
                          float* __restrict__ out)
{
    __shared__ float w[4][128];
    int tid = threadIdx.x;
    for (int idx = tid; idx < 512; idx += 128) w[idx >> 7][idx & 127] = Wfc[idx];
    __syncthreads();
    int b = blockIdx.x * 128 + tid;
    float s[4];
    #pragma unroll
    for (int cc = 0; cc < 4; ++cc) s[cc] = bfc[cc];
    #pragma unroll 4
    for (int k = 0; k < 128; ++k) {
        float h = g_h2last[b * 128 + k];
        #pragma unroll
        for (int cc = 0; cc < 4; ++cc) s[cc] = fmaf(h, w[cc][k], s[cc]);
    }
    #pragma unroll
    for (int cc = 0; cc < 4; ++cc) out[b * 4 + cc] = s[cc];
}

extern "C" void kernel_launch(void* const* d_in, const int* in_sizes, int n_in,
                              void* d_out, int out_size)
{
    (void)in_sizes; (void)n_in; (void)out_size;
    const float* x    = (const float*)d_in[0];
    const float* Wih0 = (const float*)d_in[1];
    const float* Whh0 = (const float*)d_in[2];
    const float* bih0 = (const float*)d_in[3];
    const float* bhh0 = (const float*)d_in[4];
    const float* Wih1 = (const float*)d_in[5];
    const float* Whh1 = (const float*)d_in[6];
    const float* bih1 = (const float*)d_in[7];
    const float* bhh1 = (const float*)d_in[8];
    const float* Wfc  = (const float*)d_in[9];
    const float* bfc  = (const float*)d_in[10];
    float* out = (float*)d_out;

    // layer0: K_OP = 128 (h) + 32 (x padded from 13) = 160   (8 chunks of 20)
    // layer1: K_OP = 128 (h2) + 128 (h1) = 256               (8 chunks of 32)
    const int smem0 = (160 * 128 + 2 * BC * 160 + 8 * BC * 128 + 128) * 4 + 16;
    const int smem1 = (256 * 128 + 2 * BC * 256 + 8 * BC * 128 + 128) * 4 + 16;

    cudaFuncSetAttribute((const void*)lstm_scan<13, 160, true>,
                         cudaFuncAttributeMaxDynamicSharedMemorySize, smem0);
    cudaFuncSetAttribute((const void*)lstm_scan<128, 256, false>,
                         cudaFuncAttributeMaxDynamicSharedMemorySize, smem1);

    lstm_scan<13, 160, true><<<NCLUSTERS * CLUSTER_N, THREADS, smem0>>>(
        Wih0, Whh0, bih0, bhh0, x);
    lstm_scan<128, 256, false><<<NCLUSTERS * CLUSTER_N, THREADS, smem1>>>(
        Wih1, Whh1, bih1, bhh1, nullptr);
    fc_kernel<<<4, 128>>>(Wfc, bfc, out);
}

// round 13
// speedup vs baseline: 2.1388x; 1.4697x over previous
#include <cuda_runtime.h>
#include <cooperative_groups.h>
#include <cuda_bf16.h>
#include <math.h>
#include <stdint.h>

namespace cg = cooperative_groups;

#define T_STEPS  2000
#define BATCH    512
#define CLUSTER_N 4
#define NCLUSTERS 32
#define THREADS  512
#define BC       16      // batch rows per cluster

typedef unsigned long long ull;

// Scratch: layer0 hidden sequence + final layer1 hidden state
__device__ float g_h1[(size_t)T_STEPS * BATCH * 128];
__device__ float g_h2last[BATCH * 128];

// ---------- activation approximations ----------
__device__ __forceinline__ float tanh_f(float x) {
    float y; asm("tanh.approx.f32 %0, %1;" : "=f"(y) : "f"(x)); return y;
}
__device__ __forceinline__ float sig_f(float x) {
    float e; asm("ex2.approx.f32 %0, %1;" : "=f"(e) : "f"(-1.4426950408889634f * x));
    float d = 1.0f + e, r;
    asm("rcp.approx.f32 %0, %1;" : "=f"(r) : "f"(d));
    return r;
}

// ---------- mbarrier / cluster helpers (validated in R10) ----------
__device__ __forceinline__ void mbar_init(unsigned a, unsigned cnt) {
    asm volatile("mbarrier.init.shared.b64 [%0], %1;" :: "r"(a), "r"(cnt) : "memory");
}
__device__ __forceinline__ void mbar_arrive_rank(unsigned a, unsigned rk) {
    asm volatile(
        "{\n\t.reg .b32 ra;\n\t"
        "mapa.shared::cluster.u32 ra, %0, %1;\n\t"
        "mbarrier.arrive.release.cluster.shared::cluster.b64 _, [ra];\n\t}"
        :: "r"(a), "r"(rk) : "memory");
}
__device__ __forceinline__ void mbar_wait_cl(unsigned a, unsigned par) {
    asm volatile(
        "{\n\t.reg .pred P;\n\tLW%=:\n\t"
        "mbarrier.try_wait.parity.acquire.cluster.shared::cta.b64 P, [%0], %1, 0x989680;\n\t"
        "@P bra LD%=;\n\tbra LW%=;\n\tLD%=:\n\t}"
        :: "r"(a), "r"(par) : "memory");
}
__device__ __forceinline__ unsigned mapa_rk(unsigned a, unsigned rk) {
    unsigned r; asm("mapa.shared::cluster.u32 %0, %1, %2;" : "=r"(r) : "r"(a), "r"(rk));
    return r;
}
__device__ __forceinline__ void stc_u16(unsigned a, unsigned short v) {
    asm volatile("st.shared::cluster.u16 [%0], %1;" :: "r"(a), "h"(v) : "memory");
}

// ---------- bf16 HMMA (sm_80+ baseline PTX; works on plain sm_103) ----------
__device__ __forceinline__ void mma_bf16(float* d, const unsigned* a, const unsigned* b) {
    asm volatile(
        "mma.sync.aligned.m16n8k16.row.col.f32.bf16.bf16.f32 "
        "{%0,%1,%2,%3}, {%4,%5,%6,%7}, {%8,%9}, {%0,%1,%2,%3};"
        : "+f"(d[0]), "+f"(d[1]), "+f"(d[2]), "+f"(d[3])
        : "r"(a[0]), "r"(a[1]), "r"(a[2]), "r"(a[3]), "r"(b[0]), "r"(b[1]));
}
__device__ __forceinline__ unsigned pack2(float x, float y) {
    __nv_bfloat162 v = __floats2bfloat162_rn(x, y);
    return *reinterpret_cast<unsigned*>(&v);
}

// =====================================================================
// Persistent LSTM scan. Cluster of 4 CTAs = BC=16 batch rows.
// CTA rank r owns gate-interleaved columns: local m = g*32+c -> global
// gate row g*128 + 32r + c  =>  pointwise update is fully CTA-local;
// only h (16x32 bf16 hi/lo) is replicated to the 4 peers via DSMEM.
//
// GEMM per step: D[128 m][16 n] = W[128][K] * B[K][16], bf16 HMMA
// m16n8k16, 3-pass split precision (Whi*hhi + Whi*hlo + Wlo*hhi) with
// fp32 accumulation. A fragments are STEP-INVARIANT -> kept in regs.
// 16 warps = 4 m-pairs (32 rows) x 4 K-quarters; 4 partial buffers,
// combined in the pointwise pass. B double-buffered by step parity;
// one release/acquire cluster mbarrier per step (R10 protocol).
// B rows padded to 2*K_PAD+16 bytes -> conflict-free fragment LDS.
// =====================================================================
template<int K_IN, int K_PAD, int KS, bool IS_L0>   // KS = ksteps per K-quarter
__global__ __launch_bounds__(THREADS, 1) __cluster_dims__(CLUSTER_N, 1, 1)
void lstm_scan(const float* __restrict__ W_ih, const float* __restrict__ W_hh,
               const float* __restrict__ b_ih, const float* __restrict__ b_hh,
               const float* __restrict__ x)
{
    constexpr int ROWB  = 2 * K_PAD + 16;          // bytes per B row (pad: bank-safe)
    constexpr int BB    = BC * ROWB;               // one B tile (hi or lo)
    constexpr int OPART = 4 * BB;                  // 4 tiles: [p0hi][p0lo][p1hi][p1lo]
    constexpr int PSTR  = 130;                     // partial row stride (words)
    constexpr int OBIAS = OPART + 4 * BC * PSTR * 4;
    constexpr int OMB   = OBIAS + 512;

    extern __shared__ char smraw[];
    char* base = (char*)(((uintptr_t)smraw + 127) & ~(uintptr_t)127);
    float* part   = (float*)(base + OPART);
    float* bias_s = (float*)(base + OBIAS);
    const unsigned base_u  = (unsigned)__cvta_generic_to_shared(base);
    const unsigned mb_cl_u = base_u + OMB;

    cg::cluster_group cluster = cg::this_cluster();
    const int rank = (int)cluster.block_rank();
    const int tid  = threadIdx.x;
    const int warp = tid >> 5, lane = tid & 31;
    const int cid  = blockIdx.x / CLUSTER_N;
    const int B0   = cid * BC;

    const int tg = lane >> 2, ta = lane & 3;       // mma groupID / threadInGroup
    const int mtp = warp & 3, kq = warp >> 2;      // m-pair, K-quarter

    // ---- one-time: weight fragments (hi/lo split) into REGISTERS ----
    unsigned Ahi[2][KS][4], Alo[2][KS][4];
    #pragma unroll
    for (int mt = 0; mt < 2; ++mt) {
        const int MT = mtp * 2 + mt;
        #pragma unroll
        for (int s = 0; s < KS; ++s) {
            const int kbase = (kq * KS + s) * 16;
            #pragma unroll
            for (int r = 0; r < 4; ++r) {
                int m = MT * 16 + tg + ((r & 1) ? 8 : 0);
                int k = kbase + ta * 2 + ((r & 2) ? 8 : 0);
                int grow = (m >> 5) * 128 + 32 * rank + (m & 31);
                float v0 = 0.0f, v1 = 0.0f;
                if (k < 128) v0 = W_hh[grow * 128 + k];
                else if (k - 128 < K_IN) v0 = W_ih[grow * K_IN + (k - 128)];
                if (k + 1 < 128) v1 = W_hh[grow * 128 + k + 1];
                else if (k + 1 - 128 >= 0 && k + 1 - 128 < K_IN) v1 = W_ih[grow * K_IN + (k + 1 - 128)];
                float h0 = __bfloat162float(__float2bfloat16(v0));
                float h1 = __bfloat162float(__float2bfloat16(v1));
                Ahi[mt][s][r] = pack2(h0, h1);
                Alo[mt][s][r] = pack2(v0 - h0, v1 - h1);
            }
        }
    }

    // zero all B tiles (h(0)=0, pad stays 0)
    for (int i = tid * 4; i < 4 * BB; i += THREADS * 4)
        *(unsigned*)(base + i) = 0u;
    if (tid < 128) {
        int g = tid >> 5, c = tid & 31;
        bias_s[tid] = b_ih[g * 128 + 32 * rank + c] + b_hh[g * 128 + 32 * rank + c];
    }
    if (tid == 0) mbar_init(mb_cl_u, 4);
    __syncthreads();

    unsigned peer_base[CLUSTER_N];
    #pragma unroll
    for (int d = 0; d < CLUSTER_N; ++d) peer_base[d] = mapa_rk(base_u, d);

    // pointwise mapping
    const int b  = tid >> 5;
    const int jj = tid & 31;
    const unsigned h_byte = (unsigned)(b * ROWB + (32 * rank + jj) * 2);
    float creg = 0.0f;
    const float bi0 = bias_s[jj], bi1 = bias_s[32 + jj],
                bi2 = bias_s[64 + jj], bi3 = bias_s[96 + jj];

    // input staging
    int sb = 0, si = 0;
    if constexpr (IS_L0) { sb = tid / 13; si = tid - sb * 13; }
    constexpr int NPF = IS_L0 ? 1 : 4;
    float pf[NPF];

    auto prefetch = [&](int t) {
        if constexpr (IS_L0) {
            if (tid < BC * 13)
                pf[0] = x[((size_t)(B0 + sb) * T_STEPS + t) * 13 + si];
        } else {
            #pragma unroll
            for (int i = 0; i < 4; ++i)
                pf[i] = g_h1[((size_t)t * BATCH + B0 + b) * 128 + jj + 32 * i];
        }
    };
    auto stage_input = [&](int pb) {
        char* Bh = base + (2 * pb) * BB;
        char* Bl = Bh + BB;
        if constexpr (IS_L0) {
            if (tid < BC * 13) {
                float hv = __bfloat162float(__float2bfloat16(pf[0]));
                int off = sb * ROWB + (128 + si) * 2;
                *(__nv_bfloat16*)(Bh + off) = __float2bfloat16(hv);
                *(__nv_bfloat16*)(Bl + off) = __float2bfloat16(pf[0] - hv);
            }
        } else {
            #pragma unroll
            for (int i = 0; i < 4; ++i) {
                float hv = __bfloat162float(__float2bfloat16(pf[i]));
                int off = b * ROWB + (128 + jj + 32 * i) * 2;
                *(__nv_bfloat16*)(Bh + off) = __float2bfloat16(hv);
                *(__nv_bfloat16*)(Bl + off) = __float2bfloat16(pf[i] - hv);
            }
        }
    };

    prefetch(0);
    stage_input(0);
    __syncthreads();
    cluster.sync();                     // everyone's B zeros + input staged

    for (int t = 0; t < T_STEPS; ++t) {
        const int p = t & 1;
        if (t + 1 < T_STEPS) prefetch(t + 1);

        // ---- GEMM: 3-pass split-precision bf16 HMMA ----
        float acc[2][2][4];
        #pragma unroll
        for (int i = 0; i < 2; ++i)
            #pragma unroll
            for (int j = 0; j < 2; ++j)
                #pragma unroll
                for (int r = 0; r < 4; ++r) acc[i][j][r] = 0.0f;

        const char* Bh = base + (2 * p) * BB;
        const char* Bl = Bh + BB;
        #pragma unroll
        for (int s = 0; s < KS; ++s) {
            const int kb = (kq * KS + s) * 32;          // byte offset of k*2
            #pragma unroll
            for (int nt = 0; nt < 2; ++nt) {
                const int off = (nt * 8 + tg) * ROWB + kb + ta * 4;
                unsigned bh[2], bl[2];
                bh[0] = *(const unsigned*)(Bh + off);
                bh[1] = *(const unsigned*)(Bh + off + 16);
                bl[0] = *(const unsigned*)(Bl + off);
                bl[1] = *(const unsigned*)(Bl + off + 16);
                #pragma unroll
                for (int mt = 0; mt < 2; ++mt) {
                    mma_bf16(acc[mt][nt], Ahi[mt][s], bh);
                    mma_bf16(acc[mt][nt], Ahi[mt][s], bl);
                    mma_bf16(acc[mt][nt], Alo[mt][s], bh);
                }
            }
        }

        // store partials: part[kq][n][m]
        {
            float* pq = part + kq * (BC * PSTR);
            #pragma unroll
            for (int mt = 0; mt < 2; ++mt) {
                const int m0 = (mtp * 2 + mt) * 16 + tg;
                #pragma unroll
                for (int nt = 0; nt < 2; ++nt) {
                    const int n0 = nt * 8 + 2 * ta;
                    pq[n0 * PSTR + m0]           = acc[mt][nt][0];
                    pq[(n0 + 1) * PSTR + m0]     = acc[mt][nt][1];
                    pq[n0 * PSTR + m0 + 8]       = acc[mt][nt][2];
                    pq[(n0 + 1) * PSTR + m0 + 8] = acc[mt][nt][3];
                }
            }
        }
        if (t + 1 < T_STEPS) stage_input(p ^ 1);     // input(t+1): disjoint region
        __syncthreads();

        // ---- pointwise: combine 4 partials + bias, LSTM update (CTA-local) ----
        {
            float gs0 = bi0, gs1 = bi1, gs2 = bi2, gs3 = bi3;
            #pragma unroll
            for (int q = 0; q < 4; ++q) {
                const float* pp = part + q * (BC * PSTR) + b * PSTR + jj;
                gs0 += pp[0]; gs1 += pp[32]; gs2 += pp[64]; gs3 += pp[96];
            }
            float c = sig_f(gs1) * creg + sig_f(gs0) * tanh_f(gs2);
            creg = c;
            float h = sig_f(gs3) * tanh_f(c);
            if (t + 1 < T_STEPS) {
                float hv = __bfloat162float(__float2bfloat16(h));
                unsigned short hb = __bfloat16_as_ushort(__float2bfloat16(hv));
                unsigned short lb = __bfloat16_as_ushort(__float2bfloat16(h - hv));
                const unsigned oh = (unsigned)((2 * (p ^ 1)) * BB) + h_byte;
                #pragma unroll
                for (int d = 0; d < CLUSTER_N; ++d) {
                    stc_u16(peer_base[d] + oh, hb);
                    stc_u16(peer_base[d] + oh + (unsigned)BB, lb);
                }
            }
            if constexpr (IS_L0) {
                g_h1[((size_t)t * BATCH + B0 + b) * 128 + 32 * rank + jj] = h;
            } else {
                if (t == T_STEPS - 1)
                    g_h2last[(B0 + b) * 128 + 32 * rank + jj] = h;
            }
        }

        if (t + 1 < T_STEPS) {
            __syncthreads();           // all local reads of part + DSMEM stores issued
            if (tid < 4) mbar_arrive_rank(mb_cl_u, (unsigned)tid);
            mbar_wait_cl(mb_cl_u, (unsigned)(t & 1));
        }
    }

    cluster.sync();                    // keep SMEM alive for any in-flight peer stores
}

__global__ void fc_kernel(const float* __restrict__ Wfc, const float* __restrict__ bfc,
                          float* __restrict__ out)
{
    __shared__ float w[4][128];
    int tid = threadIdx.x;
    for (int idx = tid; idx < 512; idx += 128) w[idx >> 7][idx & 127] = Wfc[idx];
    __syncthreads();
    int b = blockIdx.x * 128 + tid;
    float s[4];
    #pragma unroll
    for (int cc = 0; cc < 4; ++cc) s[cc] = bfc[cc];
    #pragma unroll 4
    for (int k = 0; k < 128; ++k) {
        float h = g_h2last[b * 128 + k];
        #pragma unroll
        for (int cc = 0; cc < 4; ++cc) s[cc] = fmaf(h, w[cc][k], s[cc]);
    }
    #pragma unroll
    for (int cc = 0; cc < 4; ++cc) out[b * 4 + cc] = s[cc];
}

extern "C" void kernel_launch(void* const* d_in, const int* in_sizes, int n_in,
                              void* d_out, int out_size)
{
    (void)in_sizes; (void)n_in; (void)out_size;
    const float* x    = (const float*)d_in[0];
    const float* Wih0 = (const float*)d_in[1];
    const float* Whh0 = (const float*)d_in[2];
    const float* bih0 = (const float*)d_in[3];
    const float* bhh0 = (const float*)d_in[4];
    const float* Wih1 = (const float*)d_in[5];
    const float* Whh1 = (const float*)d_in[6];
    const float* bih1 = (const float*)d_in[7];
    const float* bhh1 = (const float*)d_in[8];
    const float* Wfc  = (const float*)d_in[9];
    const float* bfc  = (const float*)d_in[10];
    float* out = (float*)d_out;

    // layer0: K_PAD=192 (h 0..127, x 128..140, zero pad), KS=3  (12 ksteps)
    // layer1: K_PAD=256 (h2 0..127, h1 128..255),         KS=4  (16 ksteps)
    auto smem_bytes = [](int kpad) {
        int rowb = 2 * kpad + 16;
        return 4 * (BC * rowb) + 4 * BC * 130 * 4 + 512 + 16 + 256;
    };
    const int smem0 = smem_bytes(192);
    const int smem1 = smem_bytes(256);

    cudaFuncSetAttribute((const void*)lstm_scan<13, 192, 3, true>,
                         cudaFuncAttributeMaxDynamicSharedMemorySize, smem0);
    cudaFuncSetAttribute((const void*)lstm_scan<128, 256, 4, false>,
                         cudaFuncAttributeMaxDynamicSharedMemorySize, smem1);

    lstm_scan<13, 192, 3, true><<<NCLUSTERS * CLUSTER_N, THREADS, smem0>>>(
        Wih0, Whh0, bih0, bhh0, x);
    lstm_scan<128, 256, 4, false><<<NCLUSTERS * CLUSTER_N, THREADS, smem1>>>(
        Wih1, Whh1, bih1, bhh1, nullptr);
    fc_kernel<<<4, 128>>>(Wfc, bfc, out);
}